// round 11
// baseline (speedup 1.0000x reference)
#include <cuda_runtime.h>
#include <cuda_bf16.h>
#include <stdint.h>
#include <math.h>

// Problem constants
#define NN 50000
#define EE 312500
#define DD 256
#define GN_EPS 1e-5f

// ------------------------------------------------------------------
// Device scratch (allocation-free rule: __device__ globals)
// ------------------------------------------------------------------
__device__ float g_h[NN * DD];      // GEMM out / normalized features (f32)
__device__ float g_agg[NN * DD];    // aggregation buffer / GEMM2 out
__device__ float g_stats[2 * DD];
__device__ float g_AB[2 * DD];
__device__ int   g_cnt[NN];
__device__ int   g_start[NN + 1];
__device__ int   g_cursor[NN];
__device__ int   g_src[EE];
// bf16 hi/lo weight planes, W^T [n][k]
__device__ __nv_bfloat16 g_w1h[DD * DD], g_w1l[DD * DD];
__device__ __nv_bfloat16 g_w2h[DD * DD], g_w2l[DD * DD];

// ------------------------------------------------------------------
// Helpers
// ------------------------------------------------------------------
__device__ __forceinline__ uint32_t smem_u32(const void* p) {
    uint32_t a;
    asm("{ .reg .u64 t; cvta.to.shared.u64 t, %1; cvt.u32.u64 %0, t; }"
        : "=r"(a) : "l"(p));
    return a;
}
__device__ __forceinline__ void split2(float a, float b,
                                       unsigned& hi, unsigned& lo) {
    __nv_bfloat16 ha = __float2bfloat16_rn(a);
    __nv_bfloat16 hb = __float2bfloat16_rn(b);
    __nv_bfloat16 la = __float2bfloat16_rn(a - __bfloat162float(ha));
    __nv_bfloat16 lb = __float2bfloat16_rn(b - __bfloat162float(hb));
    __nv_bfloat162 h2 = __nv_bfloat162(ha, hb);
    __nv_bfloat162 l2 = __nv_bfloat162(la, lb);
    hi = *reinterpret_cast<unsigned*>(&h2);
    lo = *reinterpret_cast<unsigned*>(&l2);
}
__device__ __forceinline__ void ldsm_x4(uint32_t addr, unsigned* r) {
    asm volatile(
        "ldmatrix.sync.aligned.m8n8.x4.shared.b16 {%0,%1,%2,%3}, [%4];"
        : "=r"(r[0]), "=r"(r[1]), "=r"(r[2]), "=r"(r[3]) : "r"(addr));
}
__device__ __forceinline__ void mma_bf16(float* c, const unsigned* a,
                                         const unsigned* b) {
    asm volatile(
        "mma.sync.aligned.m16n8k16.row.col.f32.bf16.bf16.f32 "
        "{%0,%1,%2,%3}, {%4,%5,%6,%7}, {%8,%9}, {%0,%1,%2,%3};"
        : "+f"(c[0]), "+f"(c[1]), "+f"(c[2]), "+f"(c[3])
        : "r"(a[0]), "r"(a[1]), "r"(a[2]), "r"(a[3]), "r"(b[0]), "r"(b[1]));
}

// ------------------------------------------------------------------
// Zero small state
// ------------------------------------------------------------------
__global__ void zero_small_kernel() {
    int i = blockIdx.x * blockDim.x + threadIdx.x;
    int stride = gridDim.x * blockDim.x;
    for (int k = i; k < NN; k += stride) g_cnt[k] = 0;
    if (i < 2 * DD) g_stats[i] = 0.f;
}

// ------------------------------------------------------------------
// CSR build
// ------------------------------------------------------------------
__global__ void hist_kernel(const int* __restrict__ ei) {
    int e = blockIdx.x * blockDim.x + threadIdx.x;
    if (e >= EE) return;
    atomicAdd(&g_cnt[ei[EE + e]], 1);
}
__global__ void scan_kernel() {
    __shared__ int sh[1024];
    const int t = threadIdx.x;
    const int CH = 49;
    int i0 = t * CH, i1 = min(NN, i0 + CH);
    int s = 0;
    for (int i = i0; i < i1; ++i) s += g_cnt[i];
    sh[t] = s;
    __syncthreads();
    for (int off = 1; off < 1024; off <<= 1) {
        int v = (t >= off) ? sh[t - off] : 0;
        __syncthreads();
        sh[t] += v;
        __syncthreads();
    }
    int run = sh[t] - s;
    for (int i = i0; i < i1; ++i) {
        g_start[i] = run;
        g_cursor[i] = run;
        run += g_cnt[i];
    }
    if (t == 1023) g_start[NN] = EE;
}
__global__ void fill_kernel(const int* __restrict__ ei) {
    int e = blockIdx.x * blockDim.x + threadIdx.x;
    if (e >= EE) return;
    int t = ei[EE + e];
    int pos = atomicAdd(&g_cursor[t], 1);
    g_src[pos] = ei[e];
}

// ------------------------------------------------------------------
// Convert W1,W2 -> transposed bf16 hi/lo: Wt[n][k] = W[k][n]
// ------------------------------------------------------------------
__global__ void convert_w_kernel(const float* __restrict__ W1,
                                 const float* __restrict__ W2) {
    int n = blockIdx.x;
    int k = threadIdx.x;
    float w1 = W1[k * DD + n];
    float w2 = W2[k * DD + n];
    __nv_bfloat16 h1 = __float2bfloat16_rn(w1);
    __nv_bfloat16 h2 = __float2bfloat16_rn(w2);
    g_w1h[n * DD + k] = h1;
    g_w1l[n * DD + k] = __float2bfloat16_rn(w1 - __bfloat162float(h1));
    g_w2h[n * DD + k] = h2;
    g_w2l[n * DD + k] = __float2bfloat16_rn(w2 - __bfloat162float(h2));
}

// ------------------------------------------------------------------
// Tensor GEMM (R8 core: mma.sync + ldmatrix + cp.async double buffer)
// NEW: A read directly as f32, split to bf16 hi/lo in-kernel (the
// tensor pipe is the binder; LSU/ALU absorb the conversion for free).
// C = A @ W^T; 3 hi/lo terms. CTA 128x128, 8 warps, warp 32x64, KC=32.
// SMEM pitch KP=40 halves (80B): ldmatrix phases conflict-free.
// ------------------------------------------------------------------
#define GM 128
#define GN 128
#define KC 32
#define KP 40
#define PL_B 10240                  // bytes per plane (128*40*2)
#define BUF_B (4 * PL_B)            // Ahi, Alo, Bhi, Blo
#define SMEM_TOT (2 * BUF_B)        // 81920

__global__ __launch_bounds__(256) void gemm_mma_kernel(
    const float* __restrict__ A,
    const __nv_bfloat16* __restrict__ Bh, const __nv_bfloat16* __restrict__ Bl,
    float* __restrict__ C) {
    extern __shared__ __align__(16) char smem[];
    const uint32_t sb = smem_u32(smem);
    const int tid = threadIdx.x;
    const int warp = tid >> 5, lane = tid & 31;
    const int wy = warp >> 1, wx = warp & 1;
    const int row0 = blockIdx.y * GM, col0 = blockIdx.x * GN;
    const int q = lane >> 3, r = lane & 7;

    float acc[2][8][4];
#pragma unroll
    for (int i = 0; i < 2; i++)
#pragma unroll
        for (int j = 0; j < 8; j++)
#pragma unroll
            for (int v = 0; v < 4; v++) acc[i][j][v] = 0.f;

    float4 fa[4];                   // A f32 prefetch regs
    // A mapping: i = tid + t*256 in 0..1023, row = i>>3, quad q4 = i&7
    auto ldgA = [&](int kc) {
#pragma unroll
        for (int t = 0; t < 4; t++) {
            int i = tid + t * 256;
            int row = i >> 3, q4 = i & 7;
            int grow = row0 + row;
            fa[t] = make_float4(0.f, 0.f, 0.f, 0.f);
            if (grow < NN)
                fa[t] = *reinterpret_cast<const float4*>(
                    A + (size_t)grow * DD + kc + q4 * 4);
        }
    };
    auto splitStoreA = [&](int b) {
        const uint32_t bufb = sb + b * BUF_B;
#pragma unroll
        for (int t = 0; t < 4; t++) {
            int i = tid + t * 256;
            int row = i >> 3, q4 = i & 7;
            unsigned h0, l0, h1, l1;
            split2(fa[t].x, fa[t].y, h0, l0);
            split2(fa[t].z, fa[t].w, h1, l1);
            uint32_t off = (uint32_t)(row * KP + q4 * 4) * 2;
            *reinterpret_cast<uint2*>(smem + (bufb - sb) + off) =
                make_uint2(h0, h1);
            *reinterpret_cast<uint2*>(smem + (bufb - sb) + PL_B + off) =
                make_uint2(l0, l1);
        }
    };
    auto issueB = [&](int kc, int b) {
        const uint32_t bufb = sb + b * BUF_B;
#pragma unroll
        for (int t = 0; t < 4; t++) {
            int i = tid + t * 256;          // 0..1023
            int arr = i >> 9;               // 0:Bh 1:Bl
            int rr = (i >> 2) & 127;
            int kq = i & 3;
            uint32_t dst = bufb + 2 * PL_B + arr * PL_B +
                           (uint32_t)(rr * KP + kq * 8) * 2;
            const __nv_bfloat16* g =
                (arr == 0 ? Bh : Bl) + (size_t)(col0 + rr) * DD + kc + kq * 8;
            asm volatile("cp.async.cg.shared.global [%0], [%1], 16;" ::
                         "r"(dst), "l"(g));
        }
        asm volatile("cp.async.commit_group;" ::: "memory");
    };

    ldgA(0);
    issueB(0, 0);
    splitStoreA(0);
    for (int c = 0; c < DD / KC; ++c) {
        if (c < DD / KC - 1) {
            ldgA((c + 1) * KC);
            issueB((c + 1) * KC, (c + 1) & 1);
            asm volatile("cp.async.wait_group 1;" ::: "memory");
        } else {
            asm volatile("cp.async.wait_group 0;" ::: "memory");
        }
        __syncthreads();

        const uint32_t bufb = sb + (c & 1) * BUF_B;
        const uint32_t baseA[2] = {bufb, bufb + PL_B};
        const uint32_t baseB[2] = {bufb + 2 * PL_B, bufb + 3 * PL_B};
#pragma unroll
        for (int ks = 0; ks < 2; ks++) {
            const int kb = ks * 16;
            unsigned af[2][2][4];      // [term][i][4]
#pragma unroll
            for (int tm = 0; tm < 2; tm++)
#pragma unroll
                for (int i = 0; i < 2; i++) {
                    int rowm = wy * 32 + i * 16 + (q & 1) * 8 + r;
                    int col = kb + (q >> 1) * 8;
                    ldsm_x4(baseA[tm] + (rowm * KP + col) * 2, af[tm][i]);
                }
            unsigned bf[2][4][4];      // [term][j2][4]
#pragma unroll
            for (int tm = 0; tm < 2; tm++)
#pragma unroll
                for (int j2 = 0; j2 < 4; j2++) {
                    int nn = wx * 64 + j2 * 16 + (q >> 1) * 8 + r;
                    int col = kb + (q & 1) * 8;
                    ldsm_x4(baseB[tm] + (nn * KP + col) * 2, bf[tm][j2]);
                }
            // hi*hi
#pragma unroll
            for (int i = 0; i < 2; i++)
#pragma unroll
                for (int j = 0; j < 8; j++)
                    mma_bf16(acc[i][j], af[0][i], &bf[0][j >> 1][(j & 1) * 2]);
            // hi*lo
#pragma unroll
            for (int i = 0; i < 2; i++)
#pragma unroll
                for (int j = 0; j < 8; j++)
                    mma_bf16(acc[i][j], af[0][i], &bf[1][j >> 1][(j & 1) * 2]);
            // lo*hi
#pragma unroll
            for (int i = 0; i < 2; i++)
#pragma unroll
                for (int j = 0; j < 8; j++)
                    mma_bf16(acc[i][j], af[1][i], &bf[0][j >> 1][(j & 1) * 2]);
        }
        if (c < DD / KC - 1) splitStoreA((c + 1) & 1);
        __syncthreads();
    }

    // epilogue (c-frag: rows lane>>2 and +8, cols 2*(lane&3))
    const int g2 = lane >> 2, tg = lane & 3;
#pragma unroll
    for (int i = 0; i < 2; i++) {
        int rbase = row0 + wy * 32 + i * 16 + g2;
#pragma unroll
        for (int j = 0; j < 8; j++) {
            int col = col0 + wx * 64 + j * 8 + 2 * tg;
            if (rbase < NN)
                *reinterpret_cast<float2*>(C + (size_t)rbase * DD + col) =
                    make_float2(acc[i][j][0], acc[i][j][1]);
            if (rbase + 8 < NN)
                *reinterpret_cast<float2*>(C + (size_t)(rbase + 8) * DD + col) =
                    make_float2(acc[i][j][2], acc[i][j][3]);
        }
    }
}

// ------------------------------------------------------------------
// CSR aggregation: out[n] = sum_{src in CSR[n]} feat[src]
// FINAL: +b2, tanh.  !FINAL: fused column sum/sumsq stats.
// 64 threads per node (float4 lanes), 4 nodes per 256-thread block.
// ------------------------------------------------------------------
template <bool FINAL>
__global__ void aggregate_kernel(const float* __restrict__ feat,
                                 float* __restrict__ out,
                                 const float* __restrict__ b2) {
    const int tid = threadIdx.x;
    int node = blockIdx.x * 4 + (tid >> 6);
    int d0 = (tid & 63) * 4;
    float4 acc = make_float4(0.f, 0.f, 0.f, 0.f);
    if (node < NN) {
        int j = g_start[node];
        int j1 = g_start[node + 1];
        for (; j + 2 <= j1; j += 2) {
            int s0 = g_src[j], s1 = g_src[j + 1];
            float4 v0 =
                *reinterpret_cast<const float4*>(feat + (size_t)s0 * DD + d0);
            float4 v1 =
                *reinterpret_cast<const float4*>(feat + (size_t)s1 * DD + d0);
            acc.x += v0.x + v1.x;
            acc.y += v0.y + v1.y;
            acc.z += v0.z + v1.z;
            acc.w += v0.w + v1.w;
        }
        if (j < j1) {
            float4 v0 = *reinterpret_cast<const float4*>(
                feat + (size_t)g_src[j] * DD + d0);
            acc.x += v0.x; acc.y += v0.y; acc.z += v0.z; acc.w += v0.w;
        }
        if (FINAL) {
            float4 b = *reinterpret_cast<const float4*>(b2 + d0);
            float4 o;
            o.x = tanhf(acc.x + b.x);
            o.y = tanhf(acc.y + b.y);
            o.z = tanhf(acc.z + b.z);
            o.w = tanhf(acc.w + b.w);
            *reinterpret_cast<float4*>(out + (size_t)node * DD + d0) = o;
        } else {
            *reinterpret_cast<float4*>(out + (size_t)node * DD + d0) = acc;
        }
    }
    if (!FINAL) {
        __shared__ float4 ssum[256], ssq[256];
        ssum[tid] = acc;
        ssq[tid] = make_float4(acc.x * acc.x, acc.y * acc.y, acc.z * acc.z,
                               acc.w * acc.w);
        __syncthreads();
        if (tid < 64) {
            float4 s = ssum[tid], q = ssq[tid];
#pragma unroll
            for (int g = 1; g < 4; g++) {
                float4 a = ssum[tid + g * 64], b = ssq[tid + g * 64];
                s.x += a.x; s.y += a.y; s.z += a.z; s.w += a.w;
                q.x += b.x; q.y += b.y; q.z += b.z; q.w += b.w;
            }
            atomicAdd(&g_stats[d0 + 0], s.x);
            atomicAdd(&g_stats[d0 + 1], s.y);
            atomicAdd(&g_stats[d0 + 2], s.z);
            atomicAdd(&g_stats[d0 + 3], s.w);
            atomicAdd(&g_stats[DD + d0 + 0], q.x);
            atomicAdd(&g_stats[DD + d0 + 1], q.y);
            atomicAdd(&g_stats[DD + d0 + 2], q.z);
            atomicAdd(&g_stats[DD + d0 + 3], q.w);
        }
    }
}

// ------------------------------------------------------------------
// Per-column GraphNorm affine params (b1 folded analytically)
// ------------------------------------------------------------------
__global__ void colparams_kernel(const float* __restrict__ b1,
                                 const float* __restrict__ gw,
                                 const float* __restrict__ gb,
                                 const float* __restrict__ ms) {
    int d = threadIdx.x;
    const float invN = 1.0f / (float)NN;
    float s1 = g_stats[d];
    float s2 = g_stats[DD + d];
    float b = b1[d];
    float mr = s1 * invN;
    float mean = mr + b;
    float ex2 = s2 * invN + 2.f * b * mr + b * b;
    float m_s = mean * ms[d];
    float var = ex2 - 2.f * m_s * mean + m_s * m_s;
    float inv = rsqrtf(var + GN_EPS);
    float Acol = gw[d] * inv;
    float Bcol = (b - m_s) * Acol + gb[d];
    g_AB[d] = Acol;
    g_AB[DD + d] = Bcol;
}

// ------------------------------------------------------------------
// Fused normalize + tanh -> f32 (GEMM2 splits in-kernel)
// ------------------------------------------------------------------
__global__ void norm_tanh_kernel() {
    const int n4 = NN * DD / 4;
    const float4* in4 = reinterpret_cast<const float4*>(g_agg);
    float4* out4 = reinterpret_cast<float4*>(g_h);
    const float4* A4 = reinterpret_cast<const float4*>(g_AB);
    const float4* B4 = reinterpret_cast<const float4*>(g_AB + DD);
    for (int i = blockIdx.x * blockDim.x + threadIdx.x; i < n4;
         i += gridDim.x * blockDim.x) {
        int d4 = i & (DD / 4 - 1);
        float4 v = in4[i];
        float4 a = A4[d4];
        float4 b = B4[d4];
        float4 o;
        o.x = tanhf(fmaf(v.x, a.x, b.x));
        o.y = tanhf(fmaf(v.y, a.y, b.y));
        o.z = tanhf(fmaf(v.z, a.z, b.z));
        o.w = tanhf(fmaf(v.w, a.w, b.w));
        out4[i] = o;
    }
}

// ------------------------------------------------------------------
// Launch sequence (graph-capturable: kernels only)
// ------------------------------------------------------------------
extern "C" void kernel_launch(void* const* d_in, const int* in_sizes, int n_in,
                              void* d_out, int out_size) {
    const float* x = (const float*)d_in[0];
    const int* ei = (const int*)d_in[1];
    const float* W1 = (const float*)d_in[2];
    const float* b1 = (const float*)d_in[3];
    const float* W2 = (const float*)d_in[4];
    const float* b2 = (const float*)d_in[5];
    const float* gw = (const float*)d_in[6];
    const float* gb = (const float*)d_in[7];
    const float* ms = (const float*)d_in[8];
    float* out = (float*)d_out;

    float *h, *agg;
    cudaGetSymbolAddress((void**)&h, g_h);
    cudaGetSymbolAddress((void**)&agg, g_agg);
    __nv_bfloat16 *w1h, *w1l, *w2h, *w2l;
    cudaGetSymbolAddress((void**)&w1h, g_w1h);
    cudaGetSymbolAddress((void**)&w1l, g_w1l);
    cudaGetSymbolAddress((void**)&w2h, g_w2h);
    cudaGetSymbolAddress((void**)&w2l, g_w2l);

    cudaFuncSetAttribute(gemm_mma_kernel,
                         cudaFuncAttributeMaxDynamicSharedMemorySize,
                         SMEM_TOT);

    const dim3 gemm_grid(DD / GN, (NN + GM - 1) / GM);  // (2, 391)
    const int eb = (EE + 255) / 256;
    const int ab = (NN + 3) / 4;

    // CSR build + weight conversion
    zero_small_kernel<<<256, 256>>>();
    hist_kernel<<<eb, 256>>>(ei);
    convert_w_kernel<<<DD, DD>>>(W1, W2);
    scan_kernel<<<1, 1024>>>();
    fill_kernel<<<eb, 256>>>(ei);
    // Layer 1
    gemm_mma_kernel<<<gemm_grid, 256, SMEM_TOT>>>(x, w1h, w1l, h);
    aggregate_kernel<false><<<ab, 256>>>(h, agg, b2);   // + fused stats
    colparams_kernel<<<1, 256>>>(b1, gw, gb, ms);
    norm_tanh_kernel<<<2048, 256>>>();                  // g_agg -> g_h (f32)
    // Layer 2
    gemm_mma_kernel<<<gemm_grid, 256, SMEM_TOT>>>(h, w2h, w2l, agg);
    aggregate_kernel<true><<<ab, 256>>>(agg, out, b2);  // tanh(sum + b2)
}

// round 13
// speedup vs baseline: 1.1132x; 1.1132x over previous
#include <cuda_runtime.h>
#include <cuda_bf16.h>
#include <stdint.h>
#include <math.h>

// Problem constants
#define NN 50000
#define EE 312500
#define DD 256
#define GN_EPS 1e-5f
#define NB 49                      // scan blocks: 49*1024 >= NN

// ------------------------------------------------------------------
// Device scratch (allocation-free rule: __device__ globals)
// ------------------------------------------------------------------
__device__ float g_h[NN * DD];      // GEMM out (f32)
__device__ float g_agg[NN * DD];    // aggregation buffer
__device__ float g_stats[2 * DD];
__device__ float g_AB[2 * DD];
__device__ int   g_cnt[NN];
__device__ int   g_start[NN + 1];
__device__ int   g_cursor[NN];
__device__ int   g_src[EE];
__device__ int   g_bsum[64];        // scan block totals
// bf16 hi/lo split operands (row-major [n][k])
__device__ __nv_bfloat16 g_xhi[NN * DD], g_xlo[NN * DD];
__device__ __nv_bfloat16 g_hhi[NN * DD], g_hlo[NN * DD];
__device__ __nv_bfloat16 g_w1h[DD * DD], g_w1l[DD * DD];  // W1^T [n][k]
__device__ __nv_bfloat16 g_w2h[DD * DD], g_w2l[DD * DD];  // W2^T [n][k]

// ------------------------------------------------------------------
// Helpers
// ------------------------------------------------------------------
__device__ __forceinline__ uint32_t smem_u32(const void* p) {
    uint32_t a;
    asm("{ .reg .u64 t; cvta.to.shared.u64 t, %1; cvt.u32.u64 %0, t; }"
        : "=r"(a) : "l"(p));
    return a;
}
__device__ __forceinline__ void split2(float a, float b,
                                       unsigned& hi, unsigned& lo) {
    __nv_bfloat16 ha = __float2bfloat16_rn(a);
    __nv_bfloat16 hb = __float2bfloat16_rn(b);
    __nv_bfloat16 la = __float2bfloat16_rn(a - __bfloat162float(ha));
    __nv_bfloat16 lb = __float2bfloat16_rn(b - __bfloat162float(hb));
    __nv_bfloat162 h2 = __nv_bfloat162(ha, hb);
    __nv_bfloat162 l2 = __nv_bfloat162(la, lb);
    hi = *reinterpret_cast<unsigned*>(&h2);
    lo = *reinterpret_cast<unsigned*>(&l2);
}
__device__ __forceinline__ void ldsm_x4(uint32_t addr, unsigned* r) {
    asm volatile(
        "ldmatrix.sync.aligned.m8n8.x4.shared.b16 {%0,%1,%2,%3}, [%4];"
        : "=r"(r[0]), "=r"(r[1]), "=r"(r[2]), "=r"(r[3]) : "r"(addr));
}
__device__ __forceinline__ void mma_bf16(float* c, const unsigned* a,
                                         const unsigned* b) {
    asm volatile(
        "mma.sync.aligned.m16n8k16.row.col.f32.bf16.bf16.f32 "
        "{%0,%1,%2,%3}, {%4,%5,%6,%7}, {%8,%9}, {%0,%1,%2,%3};"
        : "+f"(c[0]), "+f"(c[1]), "+f"(c[2]), "+f"(c[3])
        : "r"(a[0]), "r"(a[1]), "r"(a[2]), "r"(a[3]), "r"(b[0]), "r"(b[1]));
}

// ------------------------------------------------------------------
// Zero small state
// ------------------------------------------------------------------
__global__ void zero_small_kernel() {
    int i = blockIdx.x * blockDim.x + threadIdx.x;
    int stride = gridDim.x * blockDim.x;
    for (int k = i; k < NN; k += stride) g_cnt[k] = 0;
    if (i < 2 * DD) g_stats[i] = 0.f;
}

// ------------------------------------------------------------------
// CSR build: histogram, coalesced 3-phase scan, fill
// ------------------------------------------------------------------
__global__ void hist_kernel(const int* __restrict__ ei) {
    int e = blockIdx.x * blockDim.x + threadIdx.x;
    if (e >= EE) return;
    atomicAdd(&g_cnt[ei[EE + e]], 1);
}
// (a) per-block exclusive prefix + block total
__global__ void scan_partial_kernel() {
    __shared__ int sh[1024];
    int t = threadIdx.x;
    int i = blockIdx.x * 1024 + t;
    int v = (i < NN) ? g_cnt[i] : 0;
    sh[t] = v;
    __syncthreads();
    for (int off = 1; off < 1024; off <<= 1) {
        int u = (t >= off) ? sh[t - off] : 0;
        __syncthreads();
        sh[t] += u;
        __syncthreads();
    }
    if (i < NN) g_start[i] = sh[t] - v;   // exclusive within block
    if (t == 1023) g_bsum[blockIdx.x] = sh[1023];
}
// (b) scan the 49 block totals (1 block, 64 threads)
__global__ void scan_block_kernel() {
    __shared__ int sh[64];
    int t = threadIdx.x;
    int v = (t < NB) ? g_bsum[t] : 0;
    sh[t] = v;
    __syncthreads();
    for (int off = 1; off < 64; off <<= 1) {
        int u = (t >= off) ? sh[t - off] : 0;
        __syncthreads();
        sh[t] += u;
        __syncthreads();
    }
    if (t < NB) g_bsum[t] = sh[t] - v;    // exclusive block offset
}
// (c) add block offsets, produce g_start/g_cursor
__global__ void scan_add_kernel() {
    int t = threadIdx.x;
    int i = blockIdx.x * 1024 + t;
    if (i < NN) {
        int s = g_start[i] + g_bsum[blockIdx.x];
        g_start[i] = s;
        g_cursor[i] = s;
    }
    if (i == 0) g_start[NN] = EE;
}
__global__ void fill_kernel(const int* __restrict__ ei) {
    int e = blockIdx.x * blockDim.x + threadIdx.x;
    if (e >= EE) return;
    int t = ei[EE + e];
    int pos = atomicAdd(&g_cursor[t], 1);
    g_src[pos] = ei[e];
}

// ------------------------------------------------------------------
// Convert x -> bf16 hi/lo
// ------------------------------------------------------------------
__global__ void convert_x_kernel(const float* __restrict__ x) {
    const int n4 = NN * DD / 4;
    for (int i = blockIdx.x * blockDim.x + threadIdx.x; i < n4;
         i += gridDim.x * blockDim.x) {
        float4 v = reinterpret_cast<const float4*>(x)[i];
        unsigned h0, l0, h1, l1;
        split2(v.x, v.y, h0, l0);
        split2(v.z, v.w, h1, l1);
        reinterpret_cast<uint2*>(g_xhi)[i] = make_uint2(h0, h1);
        reinterpret_cast<uint2*>(g_xlo)[i] = make_uint2(l0, l1);
    }
}

// ------------------------------------------------------------------
// Convert W1,W2 -> transposed bf16 hi/lo: Wt[n][k] = W[k][n]
// ------------------------------------------------------------------
__global__ void convert_w_kernel(const float* __restrict__ W1,
                                 const float* __restrict__ W2) {
    int n = blockIdx.x;
    int k = threadIdx.x;
    float w1 = W1[k * DD + n];
    float w2 = W2[k * DD + n];
    __nv_bfloat16 h1 = __float2bfloat16_rn(w1);
    __nv_bfloat16 h2 = __float2bfloat16_rn(w2);
    g_w1h[n * DD + k] = h1;
    g_w1l[n * DD + k] = __float2bfloat16_rn(w1 - __bfloat162float(h1));
    g_w2h[n * DD + k] = h2;
    g_w2l[n * DD + k] = __float2bfloat16_rn(w2 - __bfloat162float(h2));
}

// ------------------------------------------------------------------
// Tensor GEMM (R8 core, UNCHANGED: mma.sync + ldmatrix + cp.async)
// C[N,256] = (Ahi+Alo) @ (Whi+Wlo)^T(stored [n][k]); 3 hi/lo terms.
// CTA 128x128, 8 warps (4x2), warp tile 32x64, K-chunk 32.
// SMEM pitch KP=40 halves (80B): ldmatrix phases conflict-free.
// ------------------------------------------------------------------
#define GM 128
#define GN 128
#define KC 32
#define KP 40
#define REG_B 10240                 // bytes per array region (128*40*2)
#define SMEM_TOT (8 * REG_B)        // 2 buffers x 4 arrays = 81920

__global__ __launch_bounds__(256) void gemm_mma_kernel(
    const __nv_bfloat16* __restrict__ Ah, const __nv_bfloat16* __restrict__ Al,
    const __nv_bfloat16* __restrict__ Bh, const __nv_bfloat16* __restrict__ Bl,
    float* __restrict__ C) {
    extern __shared__ __align__(16) char smem[];
    const uint32_t sb = smem_u32(smem);
    const int tid = threadIdx.x;
    const int warp = tid >> 5, lane = tid & 31;
    const int wy = warp >> 1, wx = warp & 1;
    const int row0 = blockIdx.y * GM, col0 = blockIdx.x * GN;
    const int q = lane >> 3, r = lane & 7;

    float acc[2][8][4];
#pragma unroll
    for (int i = 0; i < 2; i++)
#pragma unroll
        for (int j = 0; j < 8; j++)
#pragma unroll
            for (int v = 0; v < 4; v++) acc[i][j][v] = 0.f;

    auto issue = [&](int kc, int b) {
#pragma unroll
        for (int t = 0; t < 8; t++) {
            int i = tid + t * 256;          // 0..2047
            int arr = i >> 9;               // 0:Ah 1:Al 2:Bh 3:Bl
            int rr = (i & 511) >> 2;        // row 0..127
            int kq = i & 3;                 // 16B quarter
            uint32_t dst = sb + (b * 4 + arr) * REG_B + (rr * KP + kq * 8) * 2;
            if (arr < 2) {
                int grow = row0 + rr;
                const __nv_bfloat16* g =
                    (arr == 0 ? Ah : Al) + (size_t)grow * DD + kc + kq * 8;
                int ok = (grow < NN) ? 16 : 0;   // zfill OOB rows
                asm volatile(
                    "cp.async.cg.shared.global [%0], [%1], 16, %2;" ::
                    "r"(dst), "l"(g), "r"(ok));
            } else {
                const __nv_bfloat16* g =
                    (arr == 2 ? Bh : Bl) + (size_t)(col0 + rr) * DD + kc + kq * 8;
                asm volatile(
                    "cp.async.cg.shared.global [%0], [%1], 16;" ::
                    "r"(dst), "l"(g));
            }
        }
        asm volatile("cp.async.commit_group;" ::: "memory");
    };

    issue(0, 0);
    for (int c = 0; c < DD / KC; ++c) {
        if (c < DD / KC - 1) {
            issue((c + 1) * KC, (c + 1) & 1);
            asm volatile("cp.async.wait_group 1;" ::: "memory");
        } else {
            asm volatile("cp.async.wait_group 0;" ::: "memory");
        }
        __syncthreads();

        const int b = c & 1;
        const uint32_t baseA[2] = {sb + (b * 4 + 0) * REG_B,
                                   sb + (b * 4 + 1) * REG_B};
        const uint32_t baseB[2] = {sb + (b * 4 + 2) * REG_B,
                                   sb + (b * 4 + 3) * REG_B};
#pragma unroll
        for (int ks = 0; ks < 2; ks++) {
            const int kb = ks * 16;
            unsigned af[2][2][4];      // [term][i][4]
#pragma unroll
            for (int tm = 0; tm < 2; tm++)
#pragma unroll
                for (int i = 0; i < 2; i++) {
                    int rowm = wy * 32 + i * 16 + (q & 1) * 8 + r;
                    int col = kb + (q >> 1) * 8;
                    ldsm_x4(baseA[tm] + (rowm * KP + col) * 2, af[tm][i]);
                }
            unsigned bf[2][4][4];      // [term][j2][4]
#pragma unroll
            for (int tm = 0; tm < 2; tm++)
#pragma unroll
                for (int j2 = 0; j2 < 4; j2++) {
                    int nn = wx * 64 + j2 * 16 + (q >> 1) * 8 + r;
                    int col = kb + (q & 1) * 8;
                    ldsm_x4(baseB[tm] + (nn * KP + col) * 2, bf[tm][j2]);
                }
            // hi*hi
#pragma unroll
            for (int i = 0; i < 2; i++)
#pragma unroll
                for (int j = 0; j < 8; j++)
                    mma_bf16(acc[i][j], af[0][i], &bf[0][j >> 1][(j & 1) * 2]);
            // hi*lo
#pragma unroll
            for (int i = 0; i < 2; i++)
#pragma unroll
                for (int j = 0; j < 8; j++)
                    mma_bf16(acc[i][j], af[0][i], &bf[1][j >> 1][(j & 1) * 2]);
            // lo*hi
#pragma unroll
            for (int i = 0; i < 2; i++)
#pragma unroll
                for (int j = 0; j < 8; j++)
                    mma_bf16(acc[i][j], af[1][i], &bf[0][j >> 1][(j & 1) * 2]);
        }
        __syncthreads();
    }

    // epilogue (c-frag: rows lane>>2 and +8, cols 2*(lane&3))
    const int g2 = lane >> 2, tg = lane & 3;
#pragma unroll
    for (int i = 0; i < 2; i++) {
        int rbase = row0 + wy * 32 + i * 16 + g2;
#pragma unroll
        for (int j = 0; j < 8; j++) {
            int col = col0 + wx * 64 + j * 8 + 2 * tg;
            if (rbase < NN)
                *reinterpret_cast<float2*>(C + (size_t)rbase * DD + col) =
                    make_float2(acc[i][j][0], acc[i][j][1]);
            if (rbase + 8 < NN)
                *reinterpret_cast<float2*>(C + (size_t)(rbase + 8) * DD + col) =
                    make_float2(acc[i][j][2], acc[i][j][3]);
        }
    }
}

// ------------------------------------------------------------------
// CSR aggregation: out[n] = sum_{src in CSR[n]} feat[src]
// FINAL: +b2, tanh.  !FINAL: fused column sum/sumsq stats.
// ------------------------------------------------------------------
template <bool FINAL>
__global__ void aggregate_kernel(const float* __restrict__ feat,
                                 float* __restrict__ out,
                                 const float* __restrict__ b2) {
    const int tid = threadIdx.x;
    int node = blockIdx.x * 4 + (tid >> 6);
    int d0 = (tid & 63) * 4;
    float4 acc = make_float4(0.f, 0.f, 0.f, 0.f);
    if (node < NN) {
        int j = g_start[node];
        int j1 = g_start[node + 1];
        for (; j + 2 <= j1; j += 2) {
            int s0 = g_src[j], s1 = g_src[j + 1];
            float4 v0 =
                *reinterpret_cast<const float4*>(feat + (size_t)s0 * DD + d0);
            float4 v1 =
                *reinterpret_cast<const float4*>(feat + (size_t)s1 * DD + d0);
            acc.x += v0.x + v1.x;
            acc.y += v0.y + v1.y;
            acc.z += v0.z + v1.z;
            acc.w += v0.w + v1.w;
        }
        if (j < j1) {
            float4 v0 = *reinterpret_cast<const float4*>(
                feat + (size_t)g_src[j] * DD + d0);
            acc.x += v0.x; acc.y += v0.y; acc.z += v0.z; acc.w += v0.w;
        }
        if (FINAL) {
            float4 b = *reinterpret_cast<const float4*>(b2 + d0);
            float4 o;
            o.x = tanhf(acc.x + b.x);
            o.y = tanhf(acc.y + b.y);
            o.z = tanhf(acc.z + b.z);
            o.w = tanhf(acc.w + b.w);
            *reinterpret_cast<float4*>(out + (size_t)node * DD + d0) = o;
        } else {
            *reinterpret_cast<float4*>(out + (size_t)node * DD + d0) = acc;
        }
    }
    if (!FINAL) {
        __shared__ float4 ssum[256], ssq[256];
        ssum[tid] = acc;
        ssq[tid] = make_float4(acc.x * acc.x, acc.y * acc.y, acc.z * acc.z,
                               acc.w * acc.w);
        __syncthreads();
        if (tid < 64) {
            float4 s = ssum[tid], qv = ssq[tid];
#pragma unroll
            for (int g = 1; g < 4; g++) {
                float4 a = ssum[tid + g * 64], b = ssq[tid + g * 64];
                s.x += a.x; s.y += a.y; s.z += a.z; s.w += a.w;
                qv.x += b.x; qv.y += b.y; qv.z += b.z; qv.w += b.w;
            }
            atomicAdd(&g_stats[d0 + 0], s.x);
            atomicAdd(&g_stats[d0 + 1], s.y);
            atomicAdd(&g_stats[d0 + 2], s.z);
            atomicAdd(&g_stats[d0 + 3], s.w);
            atomicAdd(&g_stats[DD + d0 + 0], qv.x);
            atomicAdd(&g_stats[DD + d0 + 1], qv.y);
            atomicAdd(&g_stats[DD + d0 + 2], qv.z);
            atomicAdd(&g_stats[DD + d0 + 3], qv.w);
        }
    }
}

// ------------------------------------------------------------------
// Per-column GraphNorm affine params (b1 folded analytically)
// ------------------------------------------------------------------
__global__ void colparams_kernel(const float* __restrict__ b1,
                                 const float* __restrict__ gw,
                                 const float* __restrict__ gb,
                                 const float* __restrict__ ms) {
    int d = threadIdx.x;
    const float invN = 1.0f / (float)NN;
    float s1 = g_stats[d];
    float s2 = g_stats[DD + d];
    float b = b1[d];
    float mr = s1 * invN;
    float mean = mr + b;
    float ex2 = s2 * invN + 2.f * b * mr + b * b;
    float m_s = mean * ms[d];
    float var = ex2 - 2.f * m_s * mean + m_s * m_s;
    float inv = rsqrtf(var + GN_EPS);
    float Acol = gw[d] * inv;
    float Bcol = (b - m_s) * Acol + gb[d];
    g_AB[d] = Acol;
    g_AB[DD + d] = Bcol;
}

// ------------------------------------------------------------------
// Fused normalize + tanh -> bf16 hi/lo (h only feeds GEMM2)
// ------------------------------------------------------------------
__global__ void norm_tanh_kernel() {
    const int n4 = NN * DD / 4;
    const float4* in4 = reinterpret_cast<const float4*>(g_agg);
    const float4* A4 = reinterpret_cast<const float4*>(g_AB);
    const float4* B4 = reinterpret_cast<const float4*>(g_AB + DD);
    for (int i = blockIdx.x * blockDim.x + threadIdx.x; i < n4;
         i += gridDim.x * blockDim.x) {
        int d4 = i & (DD / 4 - 1);
        float4 v = in4[i];
        float4 a = A4[d4];
        float4 b = B4[d4];
        float ox = tanhf(fmaf(v.x, a.x, b.x));
        float oy = tanhf(fmaf(v.y, a.y, b.y));
        float oz = tanhf(fmaf(v.z, a.z, b.z));
        float ow = tanhf(fmaf(v.w, a.w, b.w));
        unsigned h0, l0, h1, l1;
        split2(ox, oy, h0, l0);
        split2(oz, ow, h1, l1);
        reinterpret_cast<uint2*>(g_hhi)[i] = make_uint2(h0, h1);
        reinterpret_cast<uint2*>(g_hlo)[i] = make_uint2(l0, l1);
    }
}

// ------------------------------------------------------------------
// Launch sequence (graph-capturable: kernels only)
// ------------------------------------------------------------------
extern "C" void kernel_launch(void* const* d_in, const int* in_sizes, int n_in,
                              void* d_out, int out_size) {
    const float* x = (const float*)d_in[0];
    const int* ei = (const int*)d_in[1];
    const float* W1 = (const float*)d_in[2];
    const float* b1 = (const float*)d_in[3];
    const float* W2 = (const float*)d_in[4];
    const float* b2 = (const float*)d_in[5];
    const float* gw = (const float*)d_in[6];
    const float* gb = (const float*)d_in[7];
    const float* ms = (const float*)d_in[8];
    float* out = (float*)d_out;

    float *h, *agg;
    cudaGetSymbolAddress((void**)&h, g_h);
    cudaGetSymbolAddress((void**)&agg, g_agg);
    __nv_bfloat16 *xhi, *xlo, *hhi, *hlo, *w1h, *w1l, *w2h, *w2l;
    cudaGetSymbolAddress((void**)&xhi, g_xhi);
    cudaGetSymbolAddress((void**)&xlo, g_xlo);
    cudaGetSymbolAddress((void**)&hhi, g_hhi);
    cudaGetSymbolAddress((void**)&hlo, g_hlo);
    cudaGetSymbolAddress((void**)&w1h, g_w1h);
    cudaGetSymbolAddress((void**)&w1l, g_w1l);
    cudaGetSymbolAddress((void**)&w2h, g_w2h);
    cudaGetSymbolAddress((void**)&w2l, g_w2l);

    cudaFuncSetAttribute(gemm_mma_kernel,
                         cudaFuncAttributeMaxDynamicSharedMemorySize,
                         SMEM_TOT);

    const dim3 gemm_grid(DD / GN, (NN + GM - 1) / GM);  // (2, 391)
    const int eb = (EE + 255) / 256;
    const int ab = (NN + 3) / 4;

    // CSR build + operand conversion
    zero_small_kernel<<<256, 256>>>();
    hist_kernel<<<eb, 256>>>(ei);
    convert_w_kernel<<<DD, DD>>>(W1, W2);
    convert_x_kernel<<<2048, 256>>>(x);
    scan_partial_kernel<<<NB, 1024>>>();
    scan_block_kernel<<<1, 64>>>();
    scan_add_kernel<<<NB, 1024>>>();
    fill_kernel<<<eb, 256>>>(ei);
    // Layer 1
    gemm_mma_kernel<<<gemm_grid, 256, SMEM_TOT>>>(xhi, xlo, w1h, w1l, h);
    aggregate_kernel<false><<<ab, 256>>>(h, agg, b2);   // + fused stats
    colparams_kernel<<<1, 256>>>(b1, gw, gb, ms);
    norm_tanh_kernel<<<2048, 256>>>();                  // -> hhi/hlo
    // Layer 2
    gemm_mma_kernel<<<gemm_grid, 256, SMEM_TOT>>>(hhi, hlo, w2h, w2l, h);
    aggregate_kernel<true><<<ab, 256>>>(h, out, b2);
}

// round 16
// speedup vs baseline: 2.6884x; 2.4150x over previous
#include <cuda_runtime.h>
#include <cuda_bf16.h>
#include <stdint.h>
#include <math.h>

// Problem constants
#define NN 50000
#define EE 312500
#define DD 256
#define GN_EPS 1e-5f
#define NB 49                      // scan blocks: 49*1024 >= NN

// ------------------------------------------------------------------
// Device scratch (allocation-free rule: __device__ globals)
// ------------------------------------------------------------------
__device__ float g_h[NN * DD];      // GEMM out (f32)
__device__ float g_agg[NN * DD];    // aggregation buffer
__device__ float g_stats[2 * DD];
__device__ float g_AB[2 * DD];
__device__ int   g_cnt[NN];
__device__ int   g_start[NN + 1];
__device__ int   g_cursor[NN];
__device__ int   g_src[EE];
__device__ int   g_bsum[64];        // scan block totals
// bf16 hi/lo split operands (row-major [n][k])
__device__ __nv_bfloat16 g_xhi[NN * DD], g_xlo[NN * DD];
__device__ __nv_bfloat16 g_hhi[NN * DD], g_hlo[NN * DD];
__device__ __nv_bfloat16 g_w1h[DD * DD], g_w1l[DD * DD];  // W1^T [n][k]
__device__ __nv_bfloat16 g_w2h[DD * DD], g_w2l[DD * DD];  // W2^T [n][k]

// ------------------------------------------------------------------
// Helpers
// ------------------------------------------------------------------
__device__ __forceinline__ uint32_t smem_u32(const void* p) {
    uint32_t a;
    asm("{ .reg .u64 t; cvta.to.shared.u64 t, %1; cvt.u32.u64 %0, t; }"
        : "=r"(a) : "l"(p));
    return a;
}
__device__ __forceinline__ void split2(float a, float b,
                                       unsigned& hi, unsigned& lo) {
    __nv_bfloat16 ha = __float2bfloat16_rn(a);
    __nv_bfloat16 hb = __float2bfloat16_rn(b);
    __nv_bfloat16 la = __float2bfloat16_rn(a - __bfloat162float(ha));
    __nv_bfloat16 lb = __float2bfloat16_rn(b - __bfloat162float(hb));
    __nv_bfloat162 h2 = __nv_bfloat162(ha, hb);
    __nv_bfloat162 l2 = __nv_bfloat162(la, lb);
    hi = *reinterpret_cast<unsigned*>(&h2);
    lo = *reinterpret_cast<unsigned*>(&l2);
}
__device__ __forceinline__ void ldsm_x4(uint32_t addr, unsigned* r) {
    asm volatile(
        "ldmatrix.sync.aligned.m8n8.x4.shared.b16 {%0,%1,%2,%3}, [%4];"
        : "=r"(r[0]), "=r"(r[1]), "=r"(r[2]), "=r"(r[3]) : "r"(addr));
}
__device__ __forceinline__ void mma_bf16(float* c, const unsigned* a,
                                         const unsigned* b) {
    asm volatile(
        "mma.sync.aligned.m16n8k16.row.col.f32.bf16.bf16.f32 "
        "{%0,%1,%2,%3}, {%4,%5,%6,%7}, {%8,%9}, {%0,%1,%2,%3};"
        : "+f"(c[0]), "+f"(c[1]), "+f"(c[2]), "+f"(c[3])
        : "r"(a[0]), "r"(a[1]), "r"(a[2]), "r"(a[3]), "r"(b[0]), "r"(b[1]));
}

// ------------------------------------------------------------------
// Zero small state (g_cnt + g_stats)
// ------------------------------------------------------------------
__global__ void zero_small_kernel() {
    int i = blockIdx.x * blockDim.x + threadIdx.x;
    if (i < NN) g_cnt[i] = 0;
    if (i < 2 * DD) g_stats[i] = 0.f;
}

// ------------------------------------------------------------------
// CSR build: histogram, coalesced 3-phase scan, fill
// ------------------------------------------------------------------
__global__ void hist_kernel(const int* __restrict__ ei) {
    int e = blockIdx.x * blockDim.x + threadIdx.x;
    if (e >= EE) return;
    atomicAdd(&g_cnt[ei[EE + e]], 1);
}
// (a) per-block exclusive prefix + block total
__global__ void scan_partial_kernel() {
    __shared__ int sh[1024];
    int t = threadIdx.x;
    int i = blockIdx.x * 1024 + t;
    int v = (i < NN) ? g_cnt[i] : 0;
    sh[t] = v;
    __syncthreads();
    for (int off = 1; off < 1024; off <<= 1) {
        int u = (t >= off) ? sh[t - off] : 0;
        __syncthreads();
        sh[t] += u;
        __syncthreads();
    }
    if (i < NN) g_start[i] = sh[t] - v;   // exclusive within block
    if (t == 1023) g_bsum[blockIdx.x] = sh[1023];
}
// (b) scan the 49 block totals (1 block, 64 threads)
__global__ void scan_block_kernel() {
    __shared__ int sh[64];
    int t = threadIdx.x;
    int v = (t < NB) ? g_bsum[t] : 0;
    sh[t] = v;
    __syncthreads();
    for (int off = 1; off < 64; off <<= 1) {
        int u = (t >= off) ? sh[t - off] : 0;
        __syncthreads();
        sh[t] += u;
        __syncthreads();
    }
    if (t < NB) g_bsum[t] = sh[t] - v;    // exclusive block offset
}
// (c) add block offsets, produce g_start/g_cursor
__global__ void scan_add_kernel() {
    int t = threadIdx.x;
    int i = blockIdx.x * 1024 + t;
    if (i < NN) {
        int s = g_start[i] + g_bsum[blockIdx.x];
        g_start[i] = s;
        g_cursor[i] = s;
    }
    if (i == 0) g_start[NN] = EE;
}
__global__ void fill_kernel(const int* __restrict__ ei) {
    int e = blockIdx.x * blockDim.x + threadIdx.x;
    if (e >= EE) return;
    int t = ei[EE + e];
    int pos = atomicAdd(&g_cursor[t], 1);
    g_src[pos] = ei[e];
}

// ------------------------------------------------------------------
// Convert x -> bf16 hi/lo
// ------------------------------------------------------------------
__global__ void convert_x_kernel(const float* __restrict__ x) {
    const int n4 = NN * DD / 4;
    for (int i = blockIdx.x * blockDim.x + threadIdx.x; i < n4;
         i += gridDim.x * blockDim.x) {
        float4 v = reinterpret_cast<const float4*>(x)[i];
        unsigned h0, l0, h1, l1;
        split2(v.x, v.y, h0, l0);
        split2(v.z, v.w, h1, l1);
        reinterpret_cast<uint2*>(g_xhi)[i] = make_uint2(h0, h1);
        reinterpret_cast<uint2*>(g_xlo)[i] = make_uint2(l0, l1);
    }
}

// ------------------------------------------------------------------
// Convert W1,W2 -> transposed bf16 hi/lo: Wt[n][k] = W[k][n]
// ------------------------------------------------------------------
__global__ void convert_w_kernel(const float* __restrict__ W1,
                                 const float* __restrict__ W2) {
    int n = blockIdx.x;
    int k = threadIdx.x;
    float w1 = W1[k * DD + n];
    float w2 = W2[k * DD + n];
    __nv_bfloat16 h1 = __float2bfloat16_rn(w1);
    __nv_bfloat16 h2 = __float2bfloat16_rn(w2);
    g_w1h[n * DD + k] = h1;
    g_w1l[n * DD + k] = __float2bfloat16_rn(w1 - __bfloat162float(h1));
    g_w2h[n * DD + k] = h2;
    g_w2l[n * DD + k] = __float2bfloat16_rn(w2 - __bfloat162float(h2));
}

// ------------------------------------------------------------------
// Tensor GEMM (R8 core, UNCHANGED: mma.sync + ldmatrix + cp.async)
// C[N,256] = (Ahi+Alo) @ (Whi+Wlo)^T(stored [n][k]); 3 hi/lo terms.
// CTA 128x128, 8 warps (4x2), warp tile 32x64, K-chunk 32.
// SMEM pitch KP=40 halves (80B): ldmatrix phases conflict-free.
// ------------------------------------------------------------------
#define GM 128
#define GN 128
#define KC 32
#define KP 40
#define REG_B 10240                 // bytes per array region (128*40*2)
#define SMEM_TOT (8 * REG_B)        // 2 buffers x 4 arrays = 81920

__global__ __launch_bounds__(256) void gemm_mma_kernel(
    const __nv_bfloat16* __restrict__ Ah, const __nv_bfloat16* __restrict__ Al,
    const __nv_bfloat16* __restrict__ Bh, const __nv_bfloat16* __restrict__ Bl,
    float* __restrict__ C) {
    extern __shared__ __align__(16) char smem[];
    const uint32_t sb = smem_u32(smem);
    const int tid = threadIdx.x;
    const int warp = tid >> 5, lane = tid & 31;
    const int wy = warp >> 1, wx = warp & 1;
    const int row0 = blockIdx.y * GM, col0 = blockIdx.x * GN;
    const int q = lane >> 3, r = lane & 7;

    float acc[2][8][4];
#pragma unroll
    for (int i = 0; i < 2; i++)
#pragma unroll
        for (int j = 0; j < 8; j++)
#pragma unroll
            for (int v = 0; v < 4; v++) acc[i][j][v] = 0.f;

    auto issue = [&](int kc, int b) {
#pragma unroll
        for (int t = 0; t < 8; t++) {
            int i = tid + t * 256;          // 0..2047
            int arr = i >> 9;               // 0:Ah 1:Al 2:Bh 3:Bl
            int rr = (i & 511) >> 2;        // row 0..127
            int kq = i & 3;                 // 16B quarter
            uint32_t dst = sb + (b * 4 + arr) * REG_B + (rr * KP + kq * 8) * 2;
            if (arr < 2) {
                int grow = row0 + rr;
                const __nv_bfloat16* g =
                    (arr == 0 ? Ah : Al) + (size_t)grow * DD + kc + kq * 8;
                int ok = (grow < NN) ? 16 : 0;   // zfill OOB rows
                asm volatile(
                    "cp.async.cg.shared.global [%0], [%1], 16, %2;" ::
                    "r"(dst), "l"(g), "r"(ok));
            } else {
                const __nv_bfloat16* g =
                    (arr == 2 ? Bh : Bl) + (size_t)(col0 + rr) * DD + kc + kq * 8;
                asm volatile(
                    "cp.async.cg.shared.global [%0], [%1], 16;" ::
                    "r"(dst), "l"(g));
            }
        }
        asm volatile("cp.async.commit_group;" ::: "memory");
    };

    issue(0, 0);
    for (int c = 0; c < DD / KC; ++c) {
        if (c < DD / KC - 1) {
            issue((c + 1) * KC, (c + 1) & 1);
            asm volatile("cp.async.wait_group 1;" ::: "memory");
        } else {
            asm volatile("cp.async.wait_group 0;" ::: "memory");
        }
        __syncthreads();

        const int b = c & 1;
        const uint32_t baseA[2] = {sb + (b * 4 + 0) * REG_B,
                                   sb + (b * 4 + 1) * REG_B};
        const uint32_t baseB[2] = {sb + (b * 4 + 2) * REG_B,
                                   sb + (b * 4 + 3) * REG_B};
#pragma unroll
        for (int ks = 0; ks < 2; ks++) {
            const int kb = ks * 16;
            unsigned af[2][2][4];      // [term][i][4]
#pragma unroll
            for (int tm = 0; tm < 2; tm++)
#pragma unroll
                for (int i = 0; i < 2; i++) {
                    int rowm = wy * 32 + i * 16 + (q & 1) * 8 + r;
                    int col = kb + (q >> 1) * 8;
                    ldsm_x4(baseA[tm] + (rowm * KP + col) * 2, af[tm][i]);
                }
            unsigned bf[2][4][4];      // [term][j2][4]
#pragma unroll
            for (int tm = 0; tm < 2; tm++)
#pragma unroll
                for (int j2 = 0; j2 < 4; j2++) {
                    int nn = wx * 64 + j2 * 16 + (q >> 1) * 8 + r;
                    int col = kb + (q & 1) * 8;
                    ldsm_x4(baseB[tm] + (nn * KP + col) * 2, bf[tm][j2]);
                }
            // hi*hi
#pragma unroll
            for (int i = 0; i < 2; i++)
#pragma unroll
                for (int j = 0; j < 8; j++)
                    mma_bf16(acc[i][j], af[0][i], &bf[0][j >> 1][(j & 1) * 2]);
            // hi*lo
#pragma unroll
            for (int i = 0; i < 2; i++)
#pragma unroll
                for (int j = 0; j < 8; j++)
                    mma_bf16(acc[i][j], af[0][i], &bf[1][j >> 1][(j & 1) * 2]);
            // lo*hi
#pragma unroll
            for (int i = 0; i < 2; i++)
#pragma unroll
                for (int j = 0; j < 8; j++)
                    mma_bf16(acc[i][j], af[1][i], &bf[0][j >> 1][(j & 1) * 2]);
        }
        __syncthreads();
    }

    // epilogue (c-frag: rows lane>>2 and +8, cols 2*(lane&3))
    const int g2 = lane >> 2, tg = lane & 3;
#pragma unroll
    for (int i = 0; i < 2; i++) {
        int rbase = row0 + wy * 32 + i * 16 + g2;
#pragma unroll
        for (int j = 0; j < 8; j++) {
            int col = col0 + wx * 64 + j * 8 + 2 * tg;
            if (rbase < NN)
                *reinterpret_cast<float2*>(C + (size_t)rbase * DD + col) =
                    make_float2(acc[i][j][0], acc[i][j][1]);
            if (rbase + 8 < NN)
                *reinterpret_cast<float2*>(C + (size_t)(rbase + 8) * DD + col) =
                    make_float2(acc[i][j][2], acc[i][j][3]);
        }
    }
}

// ------------------------------------------------------------------
// CSR aggregation: out[n] = sum_{src in CSR[n]} feat[src]  (+b2, tanh)
// ------------------------------------------------------------------
template <bool FINAL>
__global__ void aggregate_kernel(const float* __restrict__ feat,
                                 float* __restrict__ out,
                                 const float* __restrict__ b2) {
    int node = blockIdx.x * 4 + (threadIdx.x >> 6);
    if (node >= NN) return;
    int d0 = (threadIdx.x & 63) * 4;
    int j = g_start[node];
    int j1 = g_start[node + 1];
    float4 acc = make_float4(0.f, 0.f, 0.f, 0.f);
    for (; j + 2 <= j1; j += 2) {
        int s0 = g_src[j], s1 = g_src[j + 1];
        float4 v0 = *reinterpret_cast<const float4*>(feat + (size_t)s0 * DD + d0);
        float4 v1 = *reinterpret_cast<const float4*>(feat + (size_t)s1 * DD + d0);
        acc.x += v0.x + v1.x;
        acc.y += v0.y + v1.y;
        acc.z += v0.z + v1.z;
        acc.w += v0.w + v1.w;
    }
    if (j < j1) {
        float4 v0 = *reinterpret_cast<const float4*>(
            feat + (size_t)g_src[j] * DD + d0);
        acc.x += v0.x; acc.y += v0.y; acc.z += v0.z; acc.w += v0.w;
    }
    if (FINAL) {
        float4 b = *reinterpret_cast<const float4*>(b2 + d0);
        acc.x = tanhf(acc.x + b.x);
        acc.y = tanhf(acc.y + b.y);
        acc.z = tanhf(acc.z + b.z);
        acc.w = tanhf(acc.w + b.w);
    }
    *reinterpret_cast<float4*>(out + (size_t)node * DD + d0) = acc;
}

// ------------------------------------------------------------------
// Column stats (separate 256-block kernel: shallow atomic chains)
// ------------------------------------------------------------------
#define STAT_BLOCKS 256
__global__ void colstats_kernel() {
    int qd = (threadIdx.x & 63) * 4;
    int rl = threadIdx.x >> 6;
    float4 s = make_float4(0.f, 0.f, 0.f, 0.f);
    float4 s2 = make_float4(0.f, 0.f, 0.f, 0.f);
    for (int r = blockIdx.x * 4 + rl; r < NN; r += STAT_BLOCKS * 4) {
        float4 v = *reinterpret_cast<const float4*>(g_agg + (size_t)r * DD + qd);
        s.x += v.x; s.y += v.y; s.z += v.z; s.w += v.w;
        s2.x += v.x * v.x; s2.y += v.y * v.y;
        s2.z += v.z * v.z; s2.w += v.w * v.w;
    }
    __shared__ float4 shs[256], shq[256];
    shs[threadIdx.x] = s;
    shq[threadIdx.x] = s2;
    __syncthreads();
    if (threadIdx.x < 128) {
        float4 a = shs[threadIdx.x + 128], b = shq[threadIdx.x + 128];
        shs[threadIdx.x].x += a.x; shs[threadIdx.x].y += a.y;
        shs[threadIdx.x].z += a.z; shs[threadIdx.x].w += a.w;
        shq[threadIdx.x].x += b.x; shq[threadIdx.x].y += b.y;
        shq[threadIdx.x].z += b.z; shq[threadIdx.x].w += b.w;
    }
    __syncthreads();
    if (threadIdx.x < 64) {
        float4 a = shs[threadIdx.x + 64], b = shq[threadIdx.x + 64];
        float4 ss = shs[threadIdx.x], qq = shq[threadIdx.x];
        ss.x += a.x; ss.y += a.y; ss.z += a.z; ss.w += a.w;
        qq.x += b.x; qq.y += b.y; qq.z += b.z; qq.w += b.w;
        int d = threadIdx.x * 4;
        atomicAdd(&g_stats[d + 0], ss.x);
        atomicAdd(&g_stats[d + 1], ss.y);
        atomicAdd(&g_stats[d + 2], ss.z);
        atomicAdd(&g_stats[d + 3], ss.w);
        atomicAdd(&g_stats[DD + d + 0], qq.x);
        atomicAdd(&g_stats[DD + d + 1], qq.y);
        atomicAdd(&g_stats[DD + d + 2], qq.z);
        atomicAdd(&g_stats[DD + d + 3], qq.w);
    }
}

// ------------------------------------------------------------------
// Per-column GraphNorm affine params (b1 folded analytically)
// ------------------------------------------------------------------
__global__ void colparams_kernel(const float* __restrict__ b1,
                                 const float* __restrict__ gw,
                                 const float* __restrict__ gb,
                                 const float* __restrict__ ms) {
    int d = threadIdx.x;
    const float invN = 1.0f / (float)NN;
    float s1 = g_stats[d];
    float s2 = g_stats[DD + d];
    float b = b1[d];
    float mr = s1 * invN;
    float mean = mr + b;
    float ex2 = s2 * invN + 2.f * b * mr + b * b;
    float m_s = mean * ms[d];
    float var = ex2 - 2.f * m_s * mean + m_s * m_s;
    float inv = rsqrtf(var + GN_EPS);
    float Acol = gw[d] * inv;
    float Bcol = (b - m_s) * Acol + gb[d];
    g_AB[d] = Acol;
    g_AB[DD + d] = Bcol;
}

// ------------------------------------------------------------------
// Fused normalize + tanh -> bf16 hi/lo (h only feeds GEMM2)
// ------------------------------------------------------------------
__global__ void norm_tanh_kernel() {
    const int n4 = NN * DD / 4;
    const float4* in4 = reinterpret_cast<const float4*>(g_agg);
    const float4* A4 = reinterpret_cast<const float4*>(g_AB);
    const float4* B4 = reinterpret_cast<const float4*>(g_AB + DD);
    for (int i = blockIdx.x * blockDim.x + threadIdx.x; i < n4;
         i += gridDim.x * blockDim.x) {
        int d4 = i & (DD / 4 - 1);
        float4 v = in4[i];
        float4 a = A4[d4];
        float4 b = B4[d4];
        float ox = tanhf(fmaf(v.x, a.x, b.x));
        float oy = tanhf(fmaf(v.y, a.y, b.y));
        float oz = tanhf(fmaf(v.z, a.z, b.z));
        float ow = tanhf(fmaf(v.w, a.w, b.w));
        unsigned h0, l0, h1, l1;
        split2(ox, oy, h0, l0);
        split2(oz, ow, h1, l1);
        reinterpret_cast<uint2*>(g_hhi)[i] = make_uint2(h0, h1);
        reinterpret_cast<uint2*>(g_hlo)[i] = make_uint2(l0, l1);
    }
}

// ------------------------------------------------------------------
// Launch sequence (graph-capturable: kernels only)
// ------------------------------------------------------------------
extern "C" void kernel_launch(void* const* d_in, const int* in_sizes, int n_in,
                              void* d_out, int out_size) {
    const float* x = (const float*)d_in[0];
    const int* ei = (const int*)d_in[1];
    const float* W1 = (const float*)d_in[2];
    const float* b1 = (const float*)d_in[3];
    const float* W2 = (const float*)d_in[4];
    const float* b2 = (const float*)d_in[5];
    const float* gw = (const float*)d_in[6];
    const float* gb = (const float*)d_in[7];
    const float* ms = (const float*)d_in[8];
    float* out = (float*)d_out;

    float *h, *agg;
    cudaGetSymbolAddress((void**)&h, g_h);
    cudaGetSymbolAddress((void**)&agg, g_agg);
    __nv_bfloat16 *xhi, *xlo, *hhi, *hlo, *w1h, *w1l, *w2h, *w2l;
    cudaGetSymbolAddress((void**)&xhi, g_xhi);
    cudaGetSymbolAddress((void**)&xlo, g_xlo);
    cudaGetSymbolAddress((void**)&hhi, g_hhi);
    cudaGetSymbolAddress((void**)&hlo, g_hlo);
    cudaGetSymbolAddress((void**)&w1h, g_w1h);
    cudaGetSymbolAddress((void**)&w1l, g_w1l);
    cudaGetSymbolAddress((void**)&w2h, g_w2h);
    cudaGetSymbolAddress((void**)&w2l, g_w2l);

    cudaFuncSetAttribute(gemm_mma_kernel,
                         cudaFuncAttributeMaxDynamicSharedMemorySize,
                         SMEM_TOT);

    const dim3 gemm_grid(DD / GN, (NN + GM - 1) / GM);  // (2, 391)
    const int eb = (EE + 255) / 256;
    const int ab = (NN + 3) / 4;

    // CSR build + operand conversion
    zero_small_kernel<<<(NN + 255) / 256, 256>>>();
    hist_kernel<<<eb, 256>>>(ei);
    scan_partial_kernel<<<NB, 1024>>>();
    scan_block_kernel<<<1, 64>>>();
    scan_add_kernel<<<NB, 1024>>>();
    fill_kernel<<<eb, 256>>>(ei);
    convert_w_kernel<<<DD, DD>>>(W1, W2);
    convert_x_kernel<<<2048, 256>>>(x);
    // Layer 1
    gemm_mma_kernel<<<gemm_grid, 256, SMEM_TOT>>>(xhi, xlo, w1h, w1l, h);
    aggregate_kernel<false><<<ab, 256>>>(h, agg, b2);
    colstats_kernel<<<STAT_BLOCKS, 256>>>();
    colparams_kernel<<<1, 256>>>(b1, gw, gb, ms);
    norm_tanh_kernel<<<2048, 256>>>();                  // -> hhi/hlo
    // Layer 2
    gemm_mma_kernel<<<gemm_grid, 256, SMEM_TOT>>>(hhi, hlo, w2h, w2l, h);
    aggregate_kernel<true><<<ab, 256>>>(h, out, b2);
}

// round 17
// speedup vs baseline: 2.8993x; 1.0784x over previous
#include <cuda_runtime.h>
#include <cuda_bf16.h>
#include <stdint.h>
#include <math.h>

// Problem constants
#define NN 50000
#define EE 312500
#define DD 256
#define GN_EPS 1e-5f
#define NB 49                      // scan blocks: 49*1024 >= NN
#define PSLOTS 64                  // stats partial slots (chain depth 12500/64)

// ------------------------------------------------------------------
// Device scratch (allocation-free rule: __device__ globals)
// ------------------------------------------------------------------
__device__ float g_h[NN * DD];      // GEMM out (f32)
__device__ float g_agg[NN * DD];    // aggregation buffer
__device__ float g_pstats[PSLOTS * 2 * DD];  // [slot][sum256|sumsq256]
__device__ float g_AB[2 * DD];
__device__ int   g_cnt[NN];
__device__ int   g_start[NN + 1];
__device__ int   g_cursor[NN];
__device__ int   g_src[EE];
__device__ int   g_bsum[64];        // scan block totals
// bf16 hi/lo split operands (row-major [n][k])
__device__ __nv_bfloat16 g_xhi[NN * DD], g_xlo[NN * DD];
__device__ __nv_bfloat16 g_hhi[NN * DD], g_hlo[NN * DD];
__device__ __nv_bfloat16 g_w1h[DD * DD], g_w1l[DD * DD];  // W1^T [n][k]
__device__ __nv_bfloat16 g_w2h[DD * DD], g_w2l[DD * DD];  // W2^T [n][k]

// ------------------------------------------------------------------
// Helpers
// ------------------------------------------------------------------
__device__ __forceinline__ uint32_t smem_u32(const void* p) {
    uint32_t a;
    asm("{ .reg .u64 t; cvta.to.shared.u64 t, %1; cvt.u32.u64 %0, t; }"
        : "=r"(a) : "l"(p));
    return a;
}
__device__ __forceinline__ void split2(float a, float b,
                                       unsigned& hi, unsigned& lo) {
    __nv_bfloat16 ha = __float2bfloat16_rn(a);
    __nv_bfloat16 hb = __float2bfloat16_rn(b);
    __nv_bfloat16 la = __float2bfloat16_rn(a - __bfloat162float(ha));
    __nv_bfloat16 lb = __float2bfloat16_rn(b - __bfloat162float(hb));
    __nv_bfloat162 h2 = __nv_bfloat162(ha, hb);
    __nv_bfloat162 l2 = __nv_bfloat162(la, lb);
    hi = *reinterpret_cast<unsigned*>(&h2);
    lo = *reinterpret_cast<unsigned*>(&l2);
}
__device__ __forceinline__ void ldsm_x4(uint32_t addr, unsigned* r) {
    asm volatile(
        "ldmatrix.sync.aligned.m8n8.x4.shared.b16 {%0,%1,%2,%3}, [%4];"
        : "=r"(r[0]), "=r"(r[1]), "=r"(r[2]), "=r"(r[3]) : "r"(addr));
}
__device__ __forceinline__ void mma_bf16(float* c, const unsigned* a,
                                         const unsigned* b) {
    asm volatile(
        "mma.sync.aligned.m16n8k16.row.col.f32.bf16.bf16.f32 "
        "{%0,%1,%2,%3}, {%4,%5,%6,%7}, {%8,%9}, {%0,%1,%2,%3};"
        : "+f"(c[0]), "+f"(c[1]), "+f"(c[2]), "+f"(c[3])
        : "r"(a[0]), "r"(a[1]), "r"(a[2]), "r"(a[3]), "r"(b[0]), "r"(b[1]));
}

// ------------------------------------------------------------------
// Zero small state (g_cnt + g_pstats)
// ------------------------------------------------------------------
__global__ void zero_small_kernel() {
    int i = blockIdx.x * blockDim.x + threadIdx.x;
    if (i < NN) g_cnt[i] = 0;
    if (i < PSLOTS * 2 * DD) g_pstats[i] = 0.f;
}

// ------------------------------------------------------------------
// CSR build: histogram, coalesced scan (2 kernels), fill
// ------------------------------------------------------------------
__global__ void hist_kernel(const int* __restrict__ ei) {
    int e = blockIdx.x * blockDim.x + threadIdx.x;
    if (e >= EE) return;
    atomicAdd(&g_cnt[ei[EE + e]], 1);
}
// (a) per-block exclusive prefix + block total
__global__ void scan_partial_kernel() {
    __shared__ int sh[1024];
    int t = threadIdx.x;
    int i = blockIdx.x * 1024 + t;
    int v = (i < NN) ? g_cnt[i] : 0;
    sh[t] = v;
    __syncthreads();
    for (int off = 1; off < 1024; off <<= 1) {
        int u = (t >= off) ? sh[t - off] : 0;
        __syncthreads();
        sh[t] += u;
        __syncthreads();
    }
    if (i < NN) g_start[i] = sh[t] - v;   // exclusive within block
    if (t == 1023) g_bsum[blockIdx.x] = sh[1023];
}
// (b) add block offsets (redundant in-block reduce of g_bsum prefix)
__global__ void scan_add_kernel() {
    __shared__ int sh[64];
    int t = threadIdx.x;
    if (t < 64)
        sh[t] = (t < (int)blockIdx.x && t < NB) ? g_bsum[t] : 0;
    __syncthreads();
    if (t < 32) sh[t] += sh[t + 32];
    __syncthreads();
    if (t < 16) sh[t] += sh[t + 16];
    __syncthreads();
    if (t < 8) sh[t] += sh[t + 8];
    __syncthreads();
    if (t < 4) sh[t] += sh[t + 4];
    __syncthreads();
    if (t < 2) sh[t] += sh[t + 2];
    __syncthreads();
    if (t == 0) sh[0] += sh[1];
    __syncthreads();
    int off = sh[0];
    int i = blockIdx.x * 1024 + t;
    if (i < NN) {
        int s = g_start[i] + off;
        g_start[i] = s;
        g_cursor[i] = s;
    }
    if (i == 0) g_start[NN] = EE;
}
__global__ void fill_kernel(const int* __restrict__ ei) {
    int e = blockIdx.x * blockDim.x + threadIdx.x;
    if (e >= EE) return;
    int t = ei[EE + e];
    int pos = atomicAdd(&g_cursor[t], 1);
    g_src[pos] = ei[e];
}

// ------------------------------------------------------------------
// Convert W1,W2 (blocks 0..255) and x (blocks 256..) -> bf16 hi/lo
// ------------------------------------------------------------------
__global__ void convert_kernel(const float* __restrict__ x,
                               const float* __restrict__ W1,
                               const float* __restrict__ W2) {
    if (blockIdx.x < DD) {
        int n = blockIdx.x;
        int k = threadIdx.x;
        float w1 = W1[k * DD + n];
        float w2 = W2[k * DD + n];
        __nv_bfloat16 h1 = __float2bfloat16_rn(w1);
        __nv_bfloat16 h2 = __float2bfloat16_rn(w2);
        g_w1h[n * DD + k] = h1;
        g_w1l[n * DD + k] = __float2bfloat16_rn(w1 - __bfloat162float(h1));
        g_w2h[n * DD + k] = h2;
        g_w2l[n * DD + k] = __float2bfloat16_rn(w2 - __bfloat162float(h2));
        return;
    }
    const int n4 = NN * DD / 4;
    const int gsz = (gridDim.x - DD) * blockDim.x;
    for (int i = (blockIdx.x - DD) * blockDim.x + threadIdx.x; i < n4;
         i += gsz) {
        float4 v = reinterpret_cast<const float4*>(x)[i];
        unsigned h0, l0, h1, l1;
        split2(v.x, v.y, h0, l0);
        split2(v.z, v.w, h1, l1);
        reinterpret_cast<uint2*>(g_xhi)[i] = make_uint2(h0, h1);
        reinterpret_cast<uint2*>(g_xlo)[i] = make_uint2(l0, l1);
    }
}

// ------------------------------------------------------------------
// Tensor GEMM (R8 core, UNCHANGED: mma.sync + ldmatrix + cp.async)
// C[N,256] = (Ahi+Alo) @ (Whi+Wlo)^T(stored [n][k]); 3 hi/lo terms.
// CTA 128x128, 8 warps (4x2), warp tile 32x64, K-chunk 32.
// SMEM pitch KP=40 halves (80B): ldmatrix phases conflict-free.
// ------------------------------------------------------------------
#define GM 128
#define GN 128
#define KC 32
#define KP 40
#define REG_B 10240                 // bytes per array region (128*40*2)
#define SMEM_TOT (8 * REG_B)        // 2 buffers x 4 arrays = 81920

__global__ __launch_bounds__(256) void gemm_mma_kernel(
    const __nv_bfloat16* __restrict__ Ah, const __nv_bfloat16* __restrict__ Al,
    const __nv_bfloat16* __restrict__ Bh, const __nv_bfloat16* __restrict__ Bl,
    float* __restrict__ C) {
    extern __shared__ __align__(16) char smem[];
    const uint32_t sb = smem_u32(smem);
    const int tid = threadIdx.x;
    const int warp = tid >> 5, lane = tid & 31;
    const int wy = warp >> 1, wx = warp & 1;
    const int row0 = blockIdx.y * GM, col0 = blockIdx.x * GN;
    const int q = lane >> 3, r = lane & 7;

    float acc[2][8][4];
#pragma unroll
    for (int i = 0; i < 2; i++)
#pragma unroll
        for (int j = 0; j < 8; j++)
#pragma unroll
            for (int v = 0; v < 4; v++) acc[i][j][v] = 0.f;

    auto issue = [&](int kc, int b) {
#pragma unroll
        for (int t = 0; t < 8; t++) {
            int i = tid + t * 256;          // 0..2047
            int arr = i >> 9;               // 0:Ah 1:Al 2:Bh 3:Bl
            int rr = (i & 511) >> 2;        // row 0..127
            int kq = i & 3;                 // 16B quarter
            uint32_t dst = sb + (b * 4 + arr) * REG_B + (rr * KP + kq * 8) * 2;
            if (arr < 2) {
                int grow = row0 + rr;
                const __nv_bfloat16* g =
                    (arr == 0 ? Ah : Al) + (size_t)grow * DD + kc + kq * 8;
                int ok = (grow < NN) ? 16 : 0;   // zfill OOB rows
                asm volatile(
                    "cp.async.cg.shared.global [%0], [%1], 16, %2;" ::
                    "r"(dst), "l"(g), "r"(ok));
            } else {
                const __nv_bfloat16* g =
                    (arr == 2 ? Bh : Bl) + (size_t)(col0 + rr) * DD + kc + kq * 8;
                asm volatile(
                    "cp.async.cg.shared.global [%0], [%1], 16;" ::
                    "r"(dst), "l"(g));
            }
        }
        asm volatile("cp.async.commit_group;" ::: "memory");
    };

    issue(0, 0);
    for (int c = 0; c < DD / KC; ++c) {
        if (c < DD / KC - 1) {
            issue((c + 1) * KC, (c + 1) & 1);
            asm volatile("cp.async.wait_group 1;" ::: "memory");
        } else {
            asm volatile("cp.async.wait_group 0;" ::: "memory");
        }
        __syncthreads();

        const int b = c & 1;
        const uint32_t baseA[2] = {sb + (b * 4 + 0) * REG_B,
                                   sb + (b * 4 + 1) * REG_B};
        const uint32_t baseB[2] = {sb + (b * 4 + 2) * REG_B,
                                   sb + (b * 4 + 3) * REG_B};
#pragma unroll
        for (int ks = 0; ks < 2; ks++) {
            const int kb = ks * 16;
            unsigned af[2][2][4];      // [term][i][4]
#pragma unroll
            for (int tm = 0; tm < 2; tm++)
#pragma unroll
                for (int i = 0; i < 2; i++) {
                    int rowm = wy * 32 + i * 16 + (q & 1) * 8 + r;
                    int col = kb + (q >> 1) * 8;
                    ldsm_x4(baseA[tm] + (rowm * KP + col) * 2, af[tm][i]);
                }
            unsigned bf[2][4][4];      // [term][j2][4]
#pragma unroll
            for (int tm = 0; tm < 2; tm++)
#pragma unroll
                for (int j2 = 0; j2 < 4; j2++) {
                    int nn = wx * 64 + j2 * 16 + (q >> 1) * 8 + r;
                    int col = kb + (q & 1) * 8;
                    ldsm_x4(baseB[tm] + (nn * KP + col) * 2, bf[tm][j2]);
                }
            // hi*hi
#pragma unroll
            for (int i = 0; i < 2; i++)
#pragma unroll
                for (int j = 0; j < 8; j++)
                    mma_bf16(acc[i][j], af[0][i], &bf[0][j >> 1][(j & 1) * 2]);
            // hi*lo
#pragma unroll
            for (int i = 0; i < 2; i++)
#pragma unroll
                for (int j = 0; j < 8; j++)
                    mma_bf16(acc[i][j], af[0][i], &bf[1][j >> 1][(j & 1) * 2]);
            // lo*hi
#pragma unroll
            for (int i = 0; i < 2; i++)
#pragma unroll
                for (int j = 0; j < 8; j++)
                    mma_bf16(acc[i][j], af[1][i], &bf[0][j >> 1][(j & 1) * 2]);
        }
        __syncthreads();
    }

    // epilogue (c-frag: rows lane>>2 and +8, cols 2*(lane&3))
    const int g2 = lane >> 2, tg = lane & 3;
#pragma unroll
    for (int i = 0; i < 2; i++) {
        int rbase = row0 + wy * 32 + i * 16 + g2;
#pragma unroll
        for (int j = 0; j < 8; j++) {
            int col = col0 + wx * 64 + j * 8 + 2 * tg;
            if (rbase < NN)
                *reinterpret_cast<float2*>(C + (size_t)rbase * DD + col) =
                    make_float2(acc[i][j][0], acc[i][j][1]);
            if (rbase + 8 < NN)
                *reinterpret_cast<float2*>(C + (size_t)(rbase + 8) * DD + col) =
                    make_float2(acc[i][j][2], acc[i][j][3]);
        }
    }
}

// ------------------------------------------------------------------
// CSR aggregation: out[n] = sum_{src in CSR[n]} feat[src]
// FINAL: +b2, tanh.  !FINAL: slot-strided partial stats (PSLOTS
// copies -> atomic chains only ~195 deep, hidden under gather).
// NN % 4 == 0, so every block is full (no divergence at barriers).
// ------------------------------------------------------------------
template <bool FINAL>
__global__ void aggregate_kernel(const float* __restrict__ feat,
                                 float* __restrict__ out,
                                 const float* __restrict__ b2) {
    const int tid = threadIdx.x;
    int node = blockIdx.x * 4 + (tid >> 6);
    int d0 = (tid & 63) * 4;
    int j = g_start[node];
    int j1 = g_start[node + 1];
    float4 acc = make_float4(0.f, 0.f, 0.f, 0.f);
    for (; j + 2 <= j1; j += 2) {
        int s0 = g_src[j], s1 = g_src[j + 1];
        float4 v0 = *reinterpret_cast<const float4*>(feat + (size_t)s0 * DD + d0);
        float4 v1 = *reinterpret_cast<const float4*>(feat + (size_t)s1 * DD + d0);
        acc.x += v0.x + v1.x;
        acc.y += v0.y + v1.y;
        acc.z += v0.z + v1.z;
        acc.w += v0.w + v1.w;
    }
    if (j < j1) {
        float4 v0 = *reinterpret_cast<const float4*>(
            feat + (size_t)g_src[j] * DD + d0);
        acc.x += v0.x; acc.y += v0.y; acc.z += v0.z; acc.w += v0.w;
    }
    if (FINAL) {
        float4 b = *reinterpret_cast<const float4*>(b2 + d0);
        float4 o;
        o.x = tanhf(acc.x + b.x);
        o.y = tanhf(acc.y + b.y);
        o.z = tanhf(acc.z + b.z);
        o.w = tanhf(acc.w + b.w);
        *reinterpret_cast<float4*>(out + (size_t)node * DD + d0) = o;
    } else {
        *reinterpret_cast<float4*>(out + (size_t)node * DD + d0) = acc;
        __shared__ float4 ssum[256], ssq[256];
        ssum[tid] = acc;
        ssq[tid] = make_float4(acc.x * acc.x, acc.y * acc.y, acc.z * acc.z,
                               acc.w * acc.w);
        __syncthreads();
        if (tid < 64) {
            float4 s = ssum[tid], qv = ssq[tid];
#pragma unroll
            for (int g = 1; g < 4; g++) {
                float4 a = ssum[tid + g * 64], b = ssq[tid + g * 64];
                s.x += a.x; s.y += a.y; s.z += a.z; s.w += a.w;
                qv.x += b.x; qv.y += b.y; qv.z += b.z; qv.w += b.w;
            }
            float* ps = g_pstats + (blockIdx.x & (PSLOTS - 1)) * 2 * DD;
            int d = tid * 4;
            atomicAdd(&ps[d + 0], s.x);
            atomicAdd(&ps[d + 1], s.y);
            atomicAdd(&ps[d + 2], s.z);
            atomicAdd(&ps[d + 3], s.w);
            atomicAdd(&ps[DD + d + 0], qv.x);
            atomicAdd(&ps[DD + d + 1], qv.y);
            atomicAdd(&ps[DD + d + 2], qv.z);
            atomicAdd(&ps[DD + d + 3], qv.w);
        }
    }
}

// ------------------------------------------------------------------
// Per-column GraphNorm affine params: reduce PSLOTS partials + fold b1
// ------------------------------------------------------------------
__global__ void colparams_kernel(const float* __restrict__ b1,
                                 const float* __restrict__ gw,
                                 const float* __restrict__ gb,
                                 const float* __restrict__ ms) {
    int d = threadIdx.x;
    float s1 = 0.f, s2 = 0.f;
#pragma unroll 8
    for (int s = 0; s < PSLOTS; s++) {
        s1 += g_pstats[s * 2 * DD + d];
        s2 += g_pstats[s * 2 * DD + DD + d];
    }
    const float invN = 1.0f / (float)NN;
    float b = b1[d];
    float mr = s1 * invN;
    float mean = mr + b;
    float ex2 = s2 * invN + 2.f * b * mr + b * b;
    float m_s = mean * ms[d];
    float var = ex2 - 2.f * m_s * mean + m_s * m_s;
    float inv = rsqrtf(var + GN_EPS);
    float Acol = gw[d] * inv;
    float Bcol = (b - m_s) * Acol + gb[d];
    g_AB[d] = Acol;
    g_AB[DD + d] = Bcol;
}

// ------------------------------------------------------------------
// Fused normalize + tanh -> bf16 hi/lo (h only feeds GEMM2)
// ------------------------------------------------------------------
__global__ void norm_tanh_kernel() {
    const int n4 = NN * DD / 4;
    const float4* in4 = reinterpret_cast<const float4*>(g_agg);
    const float4* A4 = reinterpret_cast<const float4*>(g_AB);
    const float4* B4 = reinterpret_cast<const float4*>(g_AB + DD);
    for (int i = blockIdx.x * blockDim.x + threadIdx.x; i < n4;
         i += gridDim.x * blockDim.x) {
        int d4 = i & (DD / 4 - 1);
        float4 v = in4[i];
        float4 a = A4[d4];
        float4 b = B4[d4];
        float ox = tanhf(fmaf(v.x, a.x, b.x));
        float oy = tanhf(fmaf(v.y, a.y, b.y));
        float oz = tanhf(fmaf(v.z, a.z, b.z));
        float ow = tanhf(fmaf(v.w, a.w, b.w));
        unsigned h0, l0, h1, l1;
        split2(ox, oy, h0, l0);
        split2(oz, ow, h1, l1);
        reinterpret_cast<uint2*>(g_hhi)[i] = make_uint2(h0, h1);
        reinterpret_cast<uint2*>(g_hlo)[i] = make_uint2(l0, l1);
    }
}

// ------------------------------------------------------------------
// Launch sequence (graph-capturable: kernels only)
// ------------------------------------------------------------------
extern "C" void kernel_launch(void* const* d_in, const int* in_sizes, int n_in,
                              void* d_out, int out_size) {
    const float* x = (const float*)d_in[0];
    const int* ei = (const int*)d_in[1];
    const float* W1 = (const float*)d_in[2];
    const float* b1 = (const float*)d_in[3];
    const float* W2 = (const float*)d_in[4];
    const float* b2 = (const float*)d_in[5];
    const float* gw = (const float*)d_in[6];
    const float* gb = (const float*)d_in[7];
    const float* ms = (const float*)d_in[8];
    float* out = (float*)d_out;

    float *h, *agg;
    cudaGetSymbolAddress((void**)&h, g_h);
    cudaGetSymbolAddress((void**)&agg, g_agg);
    __nv_bfloat16 *xhi, *xlo, *hhi, *hlo, *w1h, *w1l, *w2h, *w2l;
    cudaGetSymbolAddress((void**)&xhi, g_xhi);
    cudaGetSymbolAddress((void**)&xlo, g_xlo);
    cudaGetSymbolAddress((void**)&hhi, g_hhi);
    cudaGetSymbolAddress((void**)&hlo, g_hlo);
    cudaGetSymbolAddress((void**)&w1h, g_w1h);
    cudaGetSymbolAddress((void**)&w1l, g_w1l);
    cudaGetSymbolAddress((void**)&w2h, g_w2h);
    cudaGetSymbolAddress((void**)&w2l, g_w2l);

    cudaFuncSetAttribute(gemm_mma_kernel,
                         cudaFuncAttributeMaxDynamicSharedMemorySize,
                         SMEM_TOT);

    const dim3 gemm_grid(DD / GN, (NN + GM - 1) / GM);  // (2, 391)
    const int eb = (EE + 255) / 256;
    const int ab = NN / 4;                              // 12500, exact

    // CSR build + operand conversion
    zero_small_kernel<<<(NN + 255) / 256, 256>>>();
    hist_kernel<<<eb, 256>>>(ei);
    scan_partial_kernel<<<NB, 1024>>>();
    scan_add_kernel<<<NB, 1024>>>();
    fill_kernel<<<eb, 256>>>(ei);
    convert_kernel<<<DD + 2048, 256>>>(x, W1, W2);
    // Layer 1
    gemm_mma_kernel<<<gemm_grid, 256, SMEM_TOT>>>(xhi, xlo, w1h, w1l, h);
    aggregate_kernel<false><<<ab, 256>>>(h, agg, b2);   // + partial stats
    colparams_kernel<<<1, 256>>>(b1, gw, gb, ms);
    norm_tanh_kernel<<<2048, 256>>>();                  // -> hhi/hlo
    // Layer 2
    gemm_mma_kernel<<<gemm_grid, 256, SMEM_TOT>>>(hhi, hlo, w2h, w2l, h);
    aggregate_kernel<true><<<ab, 256>>>(h, out, b2);
}